// round 10
// baseline (speedup 1.0000x reference)
#include <cuda_runtime.h>
#include <cuda_bf16.h>
#include <cuda_fp16.h>
#include <mma.h>
#include <math.h>
#include <cstdint>
#include <cstddef>

using namespace nvcuda;

#define BATCH 64
#define FRAMES 128
#define N_IN 512
#define N_HID 2048
#define ALPHA 0.5f
#define DECAY 0.5f
#define THR 0.5f

#define MEMS_ELEMS ((size_t)2 * BATCH * (FRAMES + 1) * N_HID)

// ---------------------------------------------------------------------------
// Device scratch
// ---------------------------------------------------------------------------
__device__ float g_U[2][BATCH * FRAMES][N_HID];  // x@W + bias
// A limbs (fp16, scaled 1 / 2^12 / 2^24), contiguous per (layer, ntile):
// [layer][ntile(64)][chunk(16)][limb(3)][kin(128)][col(32)]  (48MB)
__device__ __half g_Apack[(size_t)2 * 64 * 16 * 3 * 128 * 32];
// x limbs (fp16 scaled): [limb(3)][8192*512]  (24MB)
__device__ __half g_X[3][(size_t)BATCH * FRAMES * N_IN];
// W limbs (fp16 scaled): [limb(3)][2*512*2048]  (12MB)
__device__ __half g_W[3][(size_t)2 * N_IN * N_HID];
// fp16 spike scratch, ping-pong by parity: [par][layer][b][h]  (1MB)
__device__ __half g_sbf[2][2][BATCH][N_HID];
// fp32 membrane scratch, ping-pong by parity: [par][layer][b][h]  (4MB)
__device__ float g_mem[2][2][BATCH][N_HID];

// 3-limb scaled fp16 split: a = h0 + h1*2^-12 + h2*2^-24 + r, |r| ~ 2^-36|a|
__device__ __forceinline__ void split3h(float a, __half& h0, __half& h1, __half& h2)
{
    float r = a;
    h0 = __float2half_rn(r);
    r -= __half2float(h0);
    h1 = __float2half_rn(r * 4096.0f);
    r -= __half2float(h1) * (1.0f / 4096.0f);
    h2 = __float2half_rn(r * 16777216.0f);
}

__global__ void prep_A3_kernel(const float* __restrict__ A1,
                               const float* __restrict__ A2)
{
    size_t per = (size_t)N_HID * N_HID;
    size_t idx = (size_t)blockIdx.x * blockDim.x + threadIdx.x;
    if (idx >= 2 * per) return;
    int layer = (int)(idx / per);
    size_t rem = idx % per;
    int k = (int)(rem / N_HID);
    int n = (int)(rem % N_HID);
    float a = (layer ? A2 : A1)[rem];

    int nt = n >> 5, col = n & 31;
    int chunk = k >> 7, kin = k & 127;
    size_t base = ((((size_t)(layer * 64 + nt) * 16 + chunk) * 3) * 128 + kin) * 32 + col;

    __half h0, h1, h2;
    split3h(a, h0, h1, h2);
    g_Apack[base] = h0;
    g_Apack[base + (size_t)128 * 32] = h1;
    g_Apack[base + (size_t)2 * 128 * 32] = h2;
}

__global__ void prep_x3_kernel(const float* __restrict__ x)
{
    size_t total = (size_t)BATCH * FRAMES * N_IN;
    size_t idx = (size_t)blockIdx.x * blockDim.x + threadIdx.x;
    if (idx >= total) return;
    __half h0, h1, h2;
    split3h(x[idx], h0, h1, h2);
    g_X[0][idx] = h0; g_X[1][idx] = h1; g_X[2][idx] = h2;
}

__global__ void prep_W3_kernel(const float* __restrict__ W1,
                               const float* __restrict__ W2)
{
    size_t per = (size_t)N_IN * N_HID;
    size_t idx = (size_t)blockIdx.x * blockDim.x + threadIdx.x;
    if (idx >= 2 * per) return;
    float a = (idx < per) ? W1[idx] : W2[idx - per];
    __half h0, h1, h2;
    split3h(a, h0, h1, h2);
    g_W[0][idx] = h0; g_W[1][idx] = h1; g_W[2][idx] = h2;
}

// ---------------------------------------------------------------------------
// Feedforward GEMM via fp16 wmma, 6 limb-product passes (i+j<=2), per-pass
// scale 2^-12(i+j) folded into the fp32 running total.
// ---------------------------------------------------------------------------
__global__ void __launch_bounds__(256) ff_wmma_kernel(
    const float* __restrict__ b1, const float* __restrict__ b2)
{
    const int n0 = blockIdx.x * 64;
    const int m0 = blockIdx.y * 128;
    const int layer = blockIdx.z;

    __shared__ __half Xs[128][40];   // [m][k], kc=32, stride 40
    __shared__ __half Ws[32][72];    // [k][n], stride 72

    const int tid = threadIdx.x;
    const int wid = tid >> 5;
    const int wm = wid >> 1;
    const int wn = (wid & 1) * 2;

    wmma::fragment<wmma::accumulator, 16, 16, 16, float> ctot[2][2];
#pragma unroll
    for (int i = 0; i < 2; i++)
#pragma unroll
        for (int j = 0; j < 2; j++) wmma::fill_fragment(ctot[i][j], 0.0f);

    const int PI[6] = {0, 0, 1, 0, 2, 1};
    const int PJ[6] = {0, 1, 0, 2, 0, 1};
    const float PS[6] = {1.0f, 0x1p-12f, 0x1p-12f, 0x1p-24f, 0x1p-24f, 0x1p-24f};

#pragma unroll 1
    for (int p = 0; p < 6; p++) {
        const __half* __restrict__ Xsrc = &g_X[PI[p]][0];
        const __half* __restrict__ Wsrc = &g_W[PJ[p]][(size_t)layer * N_IN * N_HID];

        wmma::fragment<wmma::accumulator, 16, 16, 16, float> acc[2][2];
#pragma unroll
        for (int i = 0; i < 2; i++)
#pragma unroll
            for (int j = 0; j < 2; j++) wmma::fill_fragment(acc[i][j], 0.0f);

#pragma unroll 1
        for (int k0 = 0; k0 < N_IN; k0 += 32) {
#pragma unroll
            for (int i = 0; i < 2; i++) {
                int idx = tid + i * 256;
                int row = idx >> 2;
                int q = (idx & 3) * 8;
                *(uint4*)&Xs[row][q] =
                    *(const uint4*)&Xsrc[(size_t)(m0 + row) * N_IN + k0 + q];
            }
            {
                int row = tid >> 3;
                int cc = (tid & 7) * 8;
                *(uint4*)&Ws[row][cc] =
                    *(const uint4*)&Wsrc[(size_t)(k0 + row) * N_HID + n0 + cc];
            }
            __syncthreads();

#pragma unroll
            for (int ks = 0; ks < 2; ks++) {
                wmma::fragment<wmma::matrix_a, 16, 16, 16, __half, wmma::row_major> af[2];
                wmma::fragment<wmma::matrix_b, 16, 16, 16, __half, wmma::row_major> bf[2];
#pragma unroll
                for (int i = 0; i < 2; i++)
                    wmma::load_matrix_sync(af[i], &Xs[(2 * wm + i) * 16][ks * 16], 40);
#pragma unroll
                for (int j = 0; j < 2; j++)
                    wmma::load_matrix_sync(bf[j], &Ws[ks * 16][(wn + j) * 16], 72);
#pragma unroll
                for (int i = 0; i < 2; i++)
#pragma unroll
                    for (int j = 0; j < 2; j++)
                        wmma::mma_sync(acc[i][j], af[i], bf[j], acc[i][j]);
            }
            __syncthreads();
        }

        const float sc = PS[p];
#pragma unroll
        for (int i = 0; i < 2; i++)
#pragma unroll
            for (int j = 0; j < 2; j++)
#pragma unroll
                for (int e = 0; e < ctot[0][0].num_elements; e++)
                    ctot[i][j].x[e] += acc[i][j].x[e] * sc;
    }

    const float* __restrict__ bias = layer ? b2 : b1;
    __shared__ float Cs[128][72];
#pragma unroll
    for (int i = 0; i < 2; i++)
#pragma unroll
        for (int j = 0; j < 2; j++)
            wmma::store_matrix_sync(&Cs[(2 * wm + i) * 16][(wn + j) * 16],
                                    ctot[i][j], 72, wmma::mem_row_major);
    __syncthreads();
    float* __restrict__ U = &g_U[layer][0][0];
#pragma unroll
    for (int e = 0; e < 32; e++) {
        int flat = tid + e * 256;
        int row = flat >> 6;
        int col = flat & 63;
        U[(size_t)(m0 + row) * N_HID + n0 + col] = Cs[row][col] + bias[n0 + col];
    }
}

// ---------------------------------------------------------------------------
// Init t=0 state (outputs + both scratches, parity 0)
// ---------------------------------------------------------------------------
__global__ void init_kernel(const float* __restrict__ mem0_1,
                            const float* __restrict__ mem0_2,
                            float* __restrict__ out)
{
    float* mems = out;
    float* spikes = out + MEMS_ELEMS;
    size_t idx = (size_t)blockIdx.x * blockDim.x + threadIdx.x;
    size_t total = (size_t)2 * BATCH * N_HID;
    if (idx >= total) return;
    int l = (int)(idx / ((size_t)BATCH * N_HID));
    size_t rem = idx % ((size_t)BATCH * N_HID);
    int b = (int)(rem / N_HID);
    int h = (int)(rem % N_HID);
    const float* m0 = l ? mem0_2 : mem0_1;
    float mv = m0[(size_t)b * N_HID + h];
    size_t o = ((size_t)(l * BATCH + b) * (FRAMES + 1)) * N_HID + h;
    __stwt(&mems[o], mv);
    __stwt(&spikes[o], 0.f);
    g_mem[0][l][b][h] = mv;
    g_sbf[0][l][b][h] = __float2half(0.f);
}

// ---------------------------------------------------------------------------
// Fused pipelined step. Grid 128 = 2 layers x 64 coltiles(32). Block 512.
// 3-limb fp16 A; 16 warps: group0 limbs {0,1}, group1 limb {2}.
// KC=128, 3-stage cp.async pipeline. All d_out writes are __stwt
// (write-through, no L2 allocate) so A can stay L2-resident across steps.
// ---------------------------------------------------------------------------
#define KC 128
#define NCH (N_HID / KC)                   // 16 chunks
#define SS_STAGE_BYTES (64 * 272)          // 64 rows x 136 fp16
#define AS_STAGE_BYTES (384 * 80)          // 3 limbs x 128 k x 40 fp16
#define SS_OFF 0
#define AS_OFF (3 * SS_STAGE_BYTES)                 // 52224
#define CSA_OFF (AS_OFF + 3 * AS_STAGE_BYTES)       // 144384
#define CSB_OFF (CSA_OFF + 64 * 36 * 4)             // 153600
#define STEP_SMEM_BYTES (CSB_OFF + 64 * 36 * 4)     // 162816

__device__ __forceinline__ void cpasync16(unsigned int dst, const void* src)
{
    asm volatile("cp.async.cg.shared.global [%0], [%1], 16;\n" ::"r"(dst), "l"(src));
}

extern __shared__ char smem_buf[];

__global__ void __launch_bounds__(512) step_mma_kernel(float* __restrict__ out, int t)
{
    const int bx = blockIdx.x;
    const int layer = bx >> 6;
    const int nt = bx & 63;
    const int n0 = nt * 32;

    const int tid = threadIdx.x;
    const int wid = tid >> 5;
    const int g  = wid >> 3;       // 0: limbs {0,1}; 1: limb {2}
    const int w8 = wid & 7;
    const int wm = w8 >> 1;        // 0..3 m-tile
    const int wn = w8 & 1;         // 0..1 n-tile

    float* mems = out;
    float* spikes = out + MEMS_ELEMS;

    const __half* __restrict__ Abase =
        g_Apack + (size_t)(layer * 64 + nt) * (16 * 3 * 128 * 32);
    const __half* __restrict__ gS = &g_sbf[t & 1][layer][0][0];
    const float* __restrict__ gM = &g_mem[t & 1][layer][0][0];

    const unsigned int smem_u32 = (unsigned int)__cvta_generic_to_shared(smem_buf);

    wmma::fragment<wmma::accumulator, 16, 16, 16, float> acc[2];
#pragma unroll
    for (int i = 0; i < 2; i++) wmma::fill_fragment(acc[i], 0.0f);

    // per-thread copy maps (512 threads)
    const int aj = tid & 3;          // 16B chunk within 64B A row
    const int ar0 = tid >> 2;        // A row base (0..127)
    const int sb = tid >> 3;         // spike row (0..63)
    const int scb = tid & 7;         // spike 16B chunk base

    auto issue_stage = [&](int c, int s) {
        const char* srcA = (const char*)(Abase + (size_t)c * (3 * 128 * 32));
        unsigned int dstA = smem_u32 + AS_OFF + s * AS_STAGE_BYTES;
#pragma unroll
        for (int i = 0; i < 3; i++) {
            int r = ar0 + i * 128;   // 0..383 (A (limb,kin) row of 64B)
            cpasync16(dstA + r * 80 + aj * 16, srcA + r * 64 + aj * 16);
        }
        const char* srcS = (const char*)(gS + (size_t)sb * N_HID + c * KC);
        unsigned int dstS = smem_u32 + SS_OFF + s * SS_STAGE_BYTES + sb * 272;
#pragma unroll
        for (int i = 0; i < 2; i++) {
            int cc = scb + i * 8;    // 16 x 16B = 256B row
            cpasync16(dstS + cc * 16, srcS + cc * 16);
        }
        asm volatile("cp.async.commit_group;\n" ::: "memory");
    };

    issue_stage(0, 0);
    issue_stage(1, 1);

#pragma unroll 1
    for (int c = 0; c < NCH; c++) {
        if (c + 1 < NCH)
            asm volatile("cp.async.wait_group 1;\n" ::: "memory");
        else
            asm volatile("cp.async.wait_group 0;\n" ::: "memory");
        __syncthreads();

        if (c + 2 < NCH) issue_stage(c + 2, (c + 2) % 3);

        const int s = c % 3;
        const __half* ssb = (const __half*)(smem_buf + SS_OFF + s * SS_STAGE_BYTES);
        const __half* asb = (const __half*)(smem_buf + AS_OFF + s * AS_STAGE_BYTES);

#pragma unroll
        for (int ks = 0; ks < KC / 16; ks++) {
            wmma::fragment<wmma::matrix_a, 16, 16, 16, __half, wmma::row_major> af;
            wmma::load_matrix_sync(af, ssb + (wm * 16) * 136 + ks * 16, 136);
            if (g == 0) {
#pragma unroll
                for (int li = 0; li < 2; li++) {
                    wmma::fragment<wmma::matrix_b, 16, 16, 16, __half, wmma::row_major> bfr;
                    wmma::load_matrix_sync(bfr, asb + (li * 128 + ks * 16) * 40 + wn * 16, 40);
                    wmma::mma_sync(acc[li], af, bfr, acc[li]);
                }
            } else {
                wmma::fragment<wmma::matrix_b, 16, 16, 16, __half, wmma::row_major> bfr;
                wmma::load_matrix_sync(bfr, asb + (2 * 128 + ks * 16) * 40 + wn * 16, 40);
                wmma::mma_sync(acc[0], af, bfr, acc[0]);
            }
        }
    }

    // combine with limb scales: group0 -> c0 + c1*2^-12, group1 -> c2*2^-24
#pragma unroll
    for (int e = 0; e < acc[0].num_elements; e++)
        acc[0].x[e] = g ? acc[0].x[e] * 0x1p-24f
                        : acc[0].x[e] + acc[1].x[e] * 0x1p-12f;

    float* CsA = (float*)(smem_buf + CSA_OFF);
    float* CsB = (float*)(smem_buf + CSB_OFF);
    float* Cdst = g ? CsB : CsA;
    __syncthreads();
    wmma::store_matrix_sync(Cdst + (wm * 16) * 36 + wn * 16, acc[0], 36,
                            wmma::mem_row_major);
    __syncthreads();

    // fused LIF epilogue: p = (c0 + c1*2^-12) + c2*2^-24
    // State lives in compact scratches (L2-hot); d_out gets streaming writes.
    __half* gSn = &g_sbf[(t + 1) & 1][layer][0][0];
    float* gMn = &g_mem[(t + 1) & 1][layer][0][0];
#pragma unroll
    for (int e = 0; e < 4; e++) {
        int flat = tid + e * 512;   // 0..2047
        int b = flat >> 5;
        int hl = flat & 31;
        int h = n0 + hl;
        float p = CsA[b * 36 + hl] + CsB[b * 36 + hl];
        float u = __ldcs(&g_U[layer][b * FRAMES + t][h]);
        size_t row_t1 = ((size_t)(layer * BATCH + b) * (FRAMES + 1) + t + 1) * N_HID + h;
        float mprev = gM[(size_t)b * N_HID + h];
        float sprev = __half2float(gS[(size_t)b * N_HID + h]);
        float y = tanhf(ALPHA * p + (1.0f - ALPHA) * u);
        float mn = DECAY * mprev - THR * (1.0f - sprev) + y;
        float sn = (mn > THR) ? 1.0f : 0.0f;
        __stwt(&mems[row_t1], mn);
        __stwt(&spikes[row_t1], sn);
        gMn[(size_t)b * N_HID + h] = mn;
        gSn[(size_t)b * N_HID + h] = __float2half(sn);
    }
}

// ---------------------------------------------------------------------------
// Launch. Inputs: x, W_in1, A1, b1, W_in2, A2, b2, mem0_1, mem0_2
// ---------------------------------------------------------------------------
extern "C" void kernel_launch(void* const* d_in, const int* in_sizes, int n_in,
                              void* d_out, int out_size)
{
    const float* x      = (const float*)d_in[0];
    const float* W_in1  = (const float*)d_in[1];
    const float* A1     = (const float*)d_in[2];
    const float* b1     = (const float*)d_in[3];
    const float* W_in2  = (const float*)d_in[4];
    const float* A2     = (const float*)d_in[5];
    const float* b2     = (const float*)d_in[6];
    const float* mem0_1 = (const float*)d_in[7];
    const float* mem0_2 = (const float*)d_in[8];
    float* out = (float*)d_out;

    cudaFuncSetAttribute(step_mma_kernel,
                         cudaFuncAttributeMaxDynamicSharedMemorySize,
                         STEP_SMEM_BYTES);

    // limb packs
    {
        size_t n = (size_t)2 * N_HID * N_HID;
        prep_A3_kernel<<<(unsigned)((n + 255) / 256), 256>>>(A1, A2);
    }
    {
        size_t n = (size_t)BATCH * FRAMES * N_IN;
        prep_x3_kernel<<<(unsigned)((n + 255) / 256), 256>>>(x);
    }
    {
        size_t n = (size_t)2 * N_IN * N_HID;
        prep_W3_kernel<<<(unsigned)((n + 255) / 256), 256>>>(W_in1, W_in2);
    }

    // Feedforward drive on tensor cores (includes bias)
    {
        dim3 grid(N_HID / 64, (BATCH * FRAMES) / 128, 2);
        ff_wmma_kernel<<<grid, 256>>>(b1, b2);
    }

    // t=0 state
    {
        int total = 2 * BATCH * N_HID;
        init_kernel<<<(total + 255) / 256, 256>>>(mem0_1, mem0_2, out);
    }

    // Sequential time loop
    for (int t = 0; t < FRAMES; t++) {
        step_mma_kernel<<<128, 512, STEP_SMEM_BYTES>>>(out, t);
    }
}

// round 11
// speedup vs baseline: 1.1411x; 1.1411x over previous
#include <cuda_runtime.h>
#include <cuda_bf16.h>
#include <cuda_fp16.h>
#include <mma.h>
#include <math.h>
#include <cstdint>
#include <cstddef>

using namespace nvcuda;

#define BATCH 64
#define FRAMES 128
#define N_IN 512
#define N_HID 2048
#define ALPHA 0.5f
#define DECAY 0.5f
#define THR 0.5f

#define MEMS_ELEMS ((size_t)2 * BATCH * (FRAMES + 1) * N_HID)

// ---------------------------------------------------------------------------
// Device scratch
// ---------------------------------------------------------------------------
__device__ float g_U[2][BATCH * FRAMES][N_HID];  // x@W + bias
// A limbs (fp16, scaled 1 / 2^12 / 2^24), PRE-PADDED to the smem stage layout:
// row = 32 cols (64B) + 8 pad halves (16B) = 80B. Rows grouped
// [layer][ntile(64)][chunk(16)][limb(3)][kin(128)] -> one chunk = 384 rows
// = 30720B, fully contiguous => single TMA bulk op per stage.  (~63MB)
__device__ __half g_ApackP[(size_t)2 * 64 * 16 * 3 * 128 * 40];
// x limbs (fp16 scaled)
__device__ __half g_X[3][(size_t)BATCH * FRAMES * N_IN];
// W limbs (fp16 scaled)
__device__ __half g_W[3][(size_t)2 * N_IN * N_HID];
// fp16 spike scratch, ping-pong by parity
__device__ __half g_sbf[2][2][BATCH][N_HID];
// fp32 membrane scratch, ping-pong by parity
__device__ float g_mem[2][2][BATCH][N_HID];

// 3-limb scaled fp16 split: a = h0 + h1*2^-12 + h2*2^-24 + r, |r| ~ 2^-36|a|
__device__ __forceinline__ void split3h(float a, __half& h0, __half& h1, __half& h2)
{
    float r = a;
    h0 = __float2half_rn(r);
    r -= __half2float(h0);
    h1 = __float2half_rn(r * 4096.0f);
    r -= __half2float(h1) * (1.0f / 4096.0f);
    h2 = __float2half_rn(r * 16777216.0f);
}

__global__ void prep_A3_kernel(const float* __restrict__ A1,
                               const float* __restrict__ A2)
{
    size_t per = (size_t)N_HID * N_HID;
    size_t idx = (size_t)blockIdx.x * blockDim.x + threadIdx.x;
    if (idx >= 2 * per) return;
    int layer = (int)(idx / per);
    size_t rem = idx % per;
    int k = (int)(rem / N_HID);
    int n = (int)(rem % N_HID);
    float a = (layer ? A2 : A1)[rem];

    int nt = n >> 5, col = n & 31;
    int chunk = k >> 7, kin = k & 127;
    // limb-0 row index within the padded pack
    size_t row0 = (((size_t)(layer * 64 + nt) * 16 + chunk) * 3) * 128 + kin;

    __half h0, h1, h2;
    split3h(a, h0, h1, h2);
    g_ApackP[(row0 + 0 * 128) * 40 + col] = h0;
    g_ApackP[(row0 + 1 * 128) * 40 + col] = h1;
    g_ApackP[(row0 + 2 * 128) * 40 + col] = h2;
}

__global__ void prep_x3_kernel(const float* __restrict__ x)
{
    size_t total = (size_t)BATCH * FRAMES * N_IN;
    size_t idx = (size_t)blockIdx.x * blockDim.x + threadIdx.x;
    if (idx >= total) return;
    __half h0, h1, h2;
    split3h(x[idx], h0, h1, h2);
    g_X[0][idx] = h0; g_X[1][idx] = h1; g_X[2][idx] = h2;
}

__global__ void prep_W3_kernel(const float* __restrict__ W1,
                               const float* __restrict__ W2)
{
    size_t per = (size_t)N_IN * N_HID;
    size_t idx = (size_t)blockIdx.x * blockDim.x + threadIdx.x;
    if (idx >= 2 * per) return;
    float a = (idx < per) ? W1[idx] : W2[idx - per];
    __half h0, h1, h2;
    split3h(a, h0, h1, h2);
    g_W[0][idx] = h0; g_W[1][idx] = h1; g_W[2][idx] = h2;
}

// ---------------------------------------------------------------------------
// Feedforward GEMM via fp16 wmma, 6 limb-product passes (unchanged, proven)
// ---------------------------------------------------------------------------
__global__ void __launch_bounds__(256) ff_wmma_kernel(
    const float* __restrict__ b1, const float* __restrict__ b2)
{
    const int n0 = blockIdx.x * 64;
    const int m0 = blockIdx.y * 128;
    const int layer = blockIdx.z;

    __shared__ __half Xs[128][40];
    __shared__ __half Ws[32][72];

    const int tid = threadIdx.x;
    const int wid = tid >> 5;
    const int wm = wid >> 1;
    const int wn = (wid & 1) * 2;

    wmma::fragment<wmma::accumulator, 16, 16, 16, float> ctot[2][2];
#pragma unroll
    for (int i = 0; i < 2; i++)
#pragma unroll
        for (int j = 0; j < 2; j++) wmma::fill_fragment(ctot[i][j], 0.0f);

    const int PI[6] = {0, 0, 1, 0, 2, 1};
    const int PJ[6] = {0, 1, 0, 2, 0, 1};
    const float PS[6] = {1.0f, 0x1p-12f, 0x1p-12f, 0x1p-24f, 0x1p-24f, 0x1p-24f};

#pragma unroll 1
    for (int p = 0; p < 6; p++) {
        const __half* __restrict__ Xsrc = &g_X[PI[p]][0];
        const __half* __restrict__ Wsrc = &g_W[PJ[p]][(size_t)layer * N_IN * N_HID];

        wmma::fragment<wmma::accumulator, 16, 16, 16, float> acc[2][2];
#pragma unroll
        for (int i = 0; i < 2; i++)
#pragma unroll
            for (int j = 0; j < 2; j++) wmma::fill_fragment(acc[i][j], 0.0f);

#pragma unroll 1
        for (int k0 = 0; k0 < N_IN; k0 += 32) {
#pragma unroll
            for (int i = 0; i < 2; i++) {
                int idx = tid + i * 256;
                int row = idx >> 2;
                int q = (idx & 3) * 8;
                *(uint4*)&Xs[row][q] =
                    *(const uint4*)&Xsrc[(size_t)(m0 + row) * N_IN + k0 + q];
            }
            {
                int row = tid >> 3;
                int cc = (tid & 7) * 8;
                *(uint4*)&Ws[row][cc] =
                    *(const uint4*)&Wsrc[(size_t)(k0 + row) * N_HID + n0 + cc];
            }
            __syncthreads();

#pragma unroll
            for (int ks = 0; ks < 2; ks++) {
                wmma::fragment<wmma::matrix_a, 16, 16, 16, __half, wmma::row_major> af[2];
                wmma::fragment<wmma::matrix_b, 16, 16, 16, __half, wmma::row_major> bf[2];
#pragma unroll
                for (int i = 0; i < 2; i++)
                    wmma::load_matrix_sync(af[i], &Xs[(2 * wm + i) * 16][ks * 16], 40);
#pragma unroll
                for (int j = 0; j < 2; j++)
                    wmma::load_matrix_sync(bf[j], &Ws[ks * 16][(wn + j) * 16], 72);
#pragma unroll
                for (int i = 0; i < 2; i++)
#pragma unroll
                    for (int j = 0; j < 2; j++)
                        wmma::mma_sync(acc[i][j], af[i], bf[j], acc[i][j]);
            }
            __syncthreads();
        }

        const float sc = PS[p];
#pragma unroll
        for (int i = 0; i < 2; i++)
#pragma unroll
            for (int j = 0; j < 2; j++)
#pragma unroll
                for (int e = 0; e < ctot[0][0].num_elements; e++)
                    ctot[i][j].x[e] += acc[i][j].x[e] * sc;
    }

    const float* __restrict__ bias = layer ? b2 : b1;
    __shared__ float Cs[128][72];
#pragma unroll
    for (int i = 0; i < 2; i++)
#pragma unroll
        for (int j = 0; j < 2; j++)
            wmma::store_matrix_sync(&Cs[(2 * wm + i) * 16][(wn + j) * 16],
                                    ctot[i][j], 72, wmma::mem_row_major);
    __syncthreads();
    float* __restrict__ U = &g_U[layer][0][0];
#pragma unroll
    for (int e = 0; e < 32; e++) {
        int flat = tid + e * 256;
        int row = flat >> 6;
        int col = flat & 63;
        U[(size_t)(m0 + row) * N_HID + n0 + col] = Cs[row][col] + bias[n0 + col];
    }
}

// ---------------------------------------------------------------------------
// Init t=0 state (outputs + both scratches, parity 0)
// ---------------------------------------------------------------------------
__global__ void init_kernel(const float* __restrict__ mem0_1,
                            const float* __restrict__ mem0_2,
                            float* __restrict__ out)
{
    float* mems = out;
    float* spikes = out + MEMS_ELEMS;
    size_t idx = (size_t)blockIdx.x * blockDim.x + threadIdx.x;
    size_t total = (size_t)2 * BATCH * N_HID;
    if (idx >= total) return;
    int l = (int)(idx / ((size_t)BATCH * N_HID));
    size_t rem = idx % ((size_t)BATCH * N_HID);
    int b = (int)(rem / N_HID);
    int h = (int)(rem % N_HID);
    const float* m0 = l ? mem0_2 : mem0_1;
    float mv = m0[(size_t)b * N_HID + h];
    size_t o = ((size_t)(l * BATCH + b) * (FRAMES + 1)) * N_HID + h;
    __stwt(&mems[o], mv);
    __stwt(&spikes[o], 0.f);
    g_mem[0][l][b][h] = mv;
    g_sbf[0][l][b][h] = __float2half(0.f);
}

// ---------------------------------------------------------------------------
// Fused pipelined step. Grid 128 = 2 layers x 64 coltiles(32). Block 512.
// A staged via TMA bulk 1D (one 30720B cp.async.bulk per stage, mbarrier
// completion) — bypasses per-thread LSU/MSHR path. Spikes via cp.async.
// 4 stages, prefetch 3.
// ---------------------------------------------------------------------------
#define KC 128
#define NCH (N_HID / KC)                   // 16 chunks
#define NSTAGE 4
#define SS_STAGE_BYTES (64 * 272)          // 64 rows x 136 fp16
#define AS_STAGE_BYTES (384 * 80)          // 3 limbs x 128 k x 40 fp16 = 30720
#define SS_OFF 0
#define AS_OFF (NSTAGE * SS_STAGE_BYTES)                  // 69632
#define CSA_OFF (AS_OFF + NSTAGE * AS_STAGE_BYTES)        // 192512
#define CSB_OFF (CSA_OFF + 64 * 36 * 4)                   // 201728
#define MBAR_OFF (CSB_OFF + 64 * 36 * 4)                  // 210944
#define STEP_SMEM_BYTES (MBAR_OFF + NSTAGE * 8 + 64)      // 211040

__device__ __forceinline__ void cpasync16(unsigned int dst, const void* src)
{
    asm volatile("cp.async.cg.shared.global [%0], [%1], 16;\n" ::"r"(dst), "l"(src));
}

__device__ __forceinline__ void mbar_init(unsigned int mbar, unsigned int count)
{
    asm volatile("mbarrier.init.shared.b64 [%0], %1;\n" ::"r"(mbar), "r"(count) : "memory");
}
__device__ __forceinline__ void mbar_expect_tx(unsigned int mbar, unsigned int bytes)
{
    asm volatile("mbarrier.arrive.expect_tx.shared.b64 _, [%0], %1;\n"
                 ::"r"(mbar), "r"(bytes) : "memory");
}
__device__ __forceinline__ void tma_bulk_1d(unsigned int dst, const void* src,
                                            unsigned int bytes, unsigned int mbar)
{
    asm volatile(
        "cp.async.bulk.shared::cta.global.mbarrier::complete_tx::bytes "
        "[%0], [%1], %2, [%3];\n"
        ::"r"(dst), "l"(src), "r"(bytes), "r"(mbar) : "memory");
}
__device__ __forceinline__ void mbar_wait(unsigned int mbar, unsigned int parity)
{
    unsigned int done;
    asm volatile(
        "{\n\t"
        ".reg .pred p;\n\t"
        "mbarrier.try_wait.parity.acquire.cta.shared::cta.b64 p, [%1], %2;\n\t"
        "selp.b32 %0, 1, 0, p;\n\t"
        "}"
        : "=r"(done) : "r"(mbar), "r"(parity) : "memory");
    if (!done) {
        asm volatile(
            "{\n\t"
            ".reg .pred P1;\n\t"
            "WAIT_LOOP_%=:\n\t"
            "mbarrier.try_wait.parity.acquire.cta.shared::cta.b64 P1, [%0], %1, 0x989680;\n\t"
            "@P1 bra.uni WAIT_DONE_%=;\n\t"
            "bra.uni WAIT_LOOP_%=;\n\t"
            "WAIT_DONE_%=:\n\t"
            "}"
            ::"r"(mbar), "r"(parity) : "memory");
    }
}

extern __shared__ char smem_buf[];

__global__ void __launch_bounds__(512) step_mma_kernel(float* __restrict__ out, int t)
{
    const int bx = blockIdx.x;
    const int layer = bx >> 6;
    const int nt = bx & 63;
    const int n0 = nt * 32;

    const int tid = threadIdx.x;
    const int wid = tid >> 5;
    const int g  = wid >> 3;       // 0: limbs {0,1}; 1: limb {2}
    const int w8 = wid & 7;
    const int wm = w8 >> 1;        // 0..3 m-tile
    const int wn = w8 & 1;         // 0..1 n-tile

    float* mems = out;
    float* spikes = out + MEMS_ELEMS;

    // per-(layer,ntile) padded A pack: 16 chunks x 30720B, contiguous
    const __half* __restrict__ Abase =
        g_ApackP + (size_t)(layer * 64 + nt) * (16 * 3 * 128 * 40);
    const __half* __restrict__ gS = &g_sbf[t & 1][layer][0][0];
    const float* __restrict__ gM = &g_mem[t & 1][layer][0][0];

    const unsigned int smem_u32 = (unsigned int)__cvta_generic_to_shared(smem_buf);
    const unsigned int mbar0 = smem_u32 + MBAR_OFF;

    // init mbarriers (count=1: the single expect_tx arrival)
    if (tid == 0) {
#pragma unroll
        for (int s = 0; s < NSTAGE; s++) mbar_init(mbar0 + s * 8, 1);
    }
    __syncthreads();

    wmma::fragment<wmma::accumulator, 16, 16, 16, float> acc[2];
#pragma unroll
    for (int i = 0; i < 2; i++) wmma::fill_fragment(acc[i], 0.0f);

    // per-thread spike copy map (512 threads)
    const int sb = tid >> 3;         // spike row (0..63)
    const int scb = tid & 7;         // spike 16B chunk base

    auto issue_stage = [&](int c, int s) {
        // A chunk via single TMA bulk (elected thread)
        if (tid == 0) {
            unsigned int mb = mbar0 + s * 8;
            mbar_expect_tx(mb, AS_STAGE_BYTES);
            tma_bulk_1d(smem_u32 + AS_OFF + s * AS_STAGE_BYTES,
                        (const char*)Abase + (size_t)c * AS_STAGE_BYTES,
                        AS_STAGE_BYTES, mb);
        }
        // spikes via per-thread cp.async (small, L2-hot)
        const char* srcS = (const char*)(gS + (size_t)sb * N_HID + c * KC);
        unsigned int dstS = smem_u32 + SS_OFF + s * SS_STAGE_BYTES + sb * 272;
#pragma unroll
        for (int i = 0; i < 2; i++) {
            int cc = scb + i * 8;
            cpasync16(dstS + cc * 16, srcS + cc * 16);
        }
        asm volatile("cp.async.commit_group;\n" ::: "memory");
    };

    issue_stage(0, 0);
    issue_stage(1, 1);
    issue_stage(2, 2);

#pragma unroll 1
    for (int c = 0; c < NCH; c++) {
        // spikes for chunk c ready?
        const int rem = NCH - 1 - c;
        if (rem >= 2)
            asm volatile("cp.async.wait_group 2;\n" ::: "memory");
        else if (rem == 1)
            asm volatile("cp.async.wait_group 1;\n" ::: "memory");
        else
            asm volatile("cp.async.wait_group 0;\n" ::: "memory");
        // A chunk c ready?
        const int s = c & (NSTAGE - 1);
        mbar_wait(mbar0 + s * 8, (c >> 2) & 1);
        __syncthreads();

        if (c + 3 < NCH) issue_stage(c + 3, (c + 3) & (NSTAGE - 1));

        const __half* ssb = (const __half*)(smem_buf + SS_OFF + s * SS_STAGE_BYTES);
        const __half* asb = (const __half*)(smem_buf + AS_OFF + s * AS_STAGE_BYTES);

#pragma unroll
        for (int ks = 0; ks < KC / 16; ks++) {
            wmma::fragment<wmma::matrix_a, 16, 16, 16, __half, wmma::row_major> af;
            wmma::load_matrix_sync(af, ssb + (wm * 16) * 136 + ks * 16, 136);
            if (g == 0) {
#pragma unroll
                for (int li = 0; li < 2; li++) {
                    wmma::fragment<wmma::matrix_b, 16, 16, 16, __half, wmma::row_major> bfr;
                    wmma::load_matrix_sync(bfr, asb + (li * 128 + ks * 16) * 40 + wn * 16, 40);
                    wmma::mma_sync(acc[li], af, bfr, acc[li]);
                }
            } else {
                wmma::fragment<wmma::matrix_b, 16, 16, 16, __half, wmma::row_major> bfr;
                wmma::load_matrix_sync(bfr, asb + (2 * 128 + ks * 16) * 40 + wn * 16, 40);
                wmma::mma_sync(acc[0], af, bfr, acc[0]);
            }
        }
    }

    // combine with limb scales: group0 -> c0 + c1*2^-12, group1 -> c2*2^-24
#pragma unroll
    for (int e = 0; e < acc[0].num_elements; e++)
        acc[0].x[e] = g ? acc[0].x[e] * 0x1p-24f
                        : acc[0].x[e] + acc[1].x[e] * 0x1p-12f;

    float* CsA = (float*)(smem_buf + CSA_OFF);
    float* CsB = (float*)(smem_buf + CSB_OFF);
    float* Cdst = g ? CsB : CsA;
    __syncthreads();
    wmma::store_matrix_sync(Cdst + (wm * 16) * 36 + wn * 16, acc[0], 36,
                            wmma::mem_row_major);
    __syncthreads();

    // fused LIF epilogue: p = (c0 + c1*2^-12) + c2*2^-24
    __half* gSn = &g_sbf[(t + 1) & 1][layer][0][0];
    float* gMn = &g_mem[(t + 1) & 1][layer][0][0];
#pragma unroll
    for (int e = 0; e < 4; e++) {
        int flat = tid + e * 512;   // 0..2047
        int b = flat >> 5;
        int hl = flat & 31;
        int h = n0 + hl;
        float p = CsA[b * 36 + hl] + CsB[b * 36 + hl];
        float u = __ldcs(&g_U[layer][b * FRAMES + t][h]);
        size_t row_t1 = ((size_t)(layer * BATCH + b) * (FRAMES + 1) + t + 1) * N_HID + h;
        float mprev = gM[(size_t)b * N_HID + h];
        float sprev = __half2float(gS[(size_t)b * N_HID + h]);
        float y = tanhf(ALPHA * p + (1.0f - ALPHA) * u);
        float mn = DECAY * mprev - THR * (1.0f - sprev) + y;
        float sn = (mn > THR) ? 1.0f : 0.0f;
        __stwt(&mems[row_t1], mn);
        __stwt(&spikes[row_t1], sn);
        gMn[(size_t)b * N_HID + h] = mn;
        gSn[(size_t)b * N_HID + h] = __float2half(sn);
    }
}

// ---------------------------------------------------------------------------
// Launch. Inputs: x, W_in1, A1, b1, W_in2, A2, b2, mem0_1, mem0_2
// ---------------------------------------------------------------------------
extern "C" void kernel_launch(void* const* d_in, const int* in_sizes, int n_in,
                              void* d_out, int out_size)
{
    const float* x      = (const float*)d_in[0];
    const float* W_in1  = (const float*)d_in[1];
    const float* A1     = (const float*)d_in[2];
    const float* b1     = (const float*)d_in[3];
    const float* W_in2  = (const float*)d_in[4];
    const float* A2     = (const float*)d_in[5];
    const float* b2     = (const float*)d_in[6];
    const float* mem0_1 = (const float*)d_in[7];
    const float* mem0_2 = (const float*)d_in[8];
    float* out = (float*)d_out;

    cudaFuncSetAttribute(step_mma_kernel,
                         cudaFuncAttributeMaxDynamicSharedMemorySize,
                         STEP_SMEM_BYTES);

    // limb packs
    {
        size_t n = (size_t)2 * N_HID * N_HID;
        prep_A3_kernel<<<(unsigned)((n + 255) / 256), 256>>>(A1, A2);
    }
    {
        size_t n = (size_t)BATCH * FRAMES * N_IN;
        prep_x3_kernel<<<(unsigned)((n + 255) / 256), 256>>>(x);
    }
    {
        size_t n = (size_t)2 * N_IN * N_HID;
        prep_W3_kernel<<<(unsigned)((n + 255) / 256), 256>>>(W_in1, W_in2);
    }

    // Feedforward drive on tensor cores (includes bias)
    {
        dim3 grid(N_HID / 64, (BATCH * FRAMES) / 128, 2);
        ff_wmma_kernel<<<grid, 256>>>(b1, b2);
    }

    // t=0 state
    {
        int total = 2 * BATCH * N_HID;
        init_kernel<<<(total + 255) / 256, 256>>>(mem0_1, mem0_2, out);
    }

    // Sequential time loop
    for (int t = 0; t < FRAMES; t++) {
        step_mma_kernel<<<128, 512, STEP_SMEM_BYTES>>>(out, t);
    }
}

// round 12
// speedup vs baseline: 1.1425x; 1.0012x over previous
#include <cuda_runtime.h>
#include <cuda_bf16.h>
#include <cuda_fp16.h>
#include <mma.h>
#include <math.h>
#include <cstdint>
#include <cstddef>

using namespace nvcuda;

#define BATCH 64
#define FRAMES 128
#define N_IN 512
#define N_HID 2048
#define ALPHA 0.5f
#define DECAY 0.5f
#define THR 0.5f

#define MEMS_ELEMS ((size_t)2 * BATCH * (FRAMES + 1) * N_HID)

// ---------------------------------------------------------------------------
// Device scratch
// ---------------------------------------------------------------------------
__device__ float g_U[2][BATCH * FRAMES][N_HID];  // x@W + bias
// A limbs (fp16, scaled 1 / 2^12 / 2^24), PRE-PADDED to the smem stage layout:
// row = 32 cols (64B) + 8 pad halves (16B) = 80B. Rows grouped
// [layer][ntile(64)][chunk(16)][limb(3)][kin(128)] -> one chunk = 384 rows
// = 30720B, fully contiguous => single TMA bulk op per stage.  (~63MB)
__device__ __half g_ApackP[(size_t)2 * 64 * 16 * 3 * 128 * 40];
// x limbs (fp16 scaled)
__device__ __half g_X[3][(size_t)BATCH * FRAMES * N_IN];
// W limbs (fp16 scaled)
__device__ __half g_W[3][(size_t)2 * N_IN * N_HID];
// fp16 spike scratch, ping-pong by parity
__device__ __half g_sbf[2][2][BATCH][N_HID];
// fp32 membrane scratch, ping-pong by parity
__device__ float g_mem[2][2][BATCH][N_HID];

// 3-limb scaled fp16 split: a = h0 + h1*2^-12 + h2*2^-24 + r, |r| ~ 2^-36|a|
__device__ __forceinline__ void split3h(float a, __half& h0, __half& h1, __half& h2)
{
    float r = a;
    h0 = __float2half_rn(r);
    r -= __half2float(h0);
    h1 = __float2half_rn(r * 4096.0f);
    r -= __half2float(h1) * (1.0f / 4096.0f);
    h2 = __float2half_rn(r * 16777216.0f);
}

__global__ void prep_A3_kernel(const float* __restrict__ A1,
                               const float* __restrict__ A2)
{
    size_t per = (size_t)N_HID * N_HID;
    size_t idx = (size_t)blockIdx.x * blockDim.x + threadIdx.x;
    if (idx >= 2 * per) return;
    int layer = (int)(idx / per);
    size_t rem = idx % per;
    int k = (int)(rem / N_HID);
    int n = (int)(rem % N_HID);
    float a = (layer ? A2 : A1)[rem];

    int nt = n >> 5, col = n & 31;
    int chunk = k >> 7, kin = k & 127;
    size_t row0 = (((size_t)(layer * 64 + nt) * 16 + chunk) * 3) * 128 + kin;

    __half h0, h1, h2;
    split3h(a, h0, h1, h2);
    g_ApackP[(row0 + 0 * 128) * 40 + col] = h0;
    g_ApackP[(row0 + 1 * 128) * 40 + col] = h1;
    g_ApackP[(row0 + 2 * 128) * 40 + col] = h2;
}

__global__ void prep_x3_kernel(const float* __restrict__ x)
{
    size_t total = (size_t)BATCH * FRAMES * N_IN;
    size_t idx = (size_t)blockIdx.x * blockDim.x + threadIdx.x;
    if (idx >= total) return;
    __half h0, h1, h2;
    split3h(x[idx], h0, h1, h2);
    g_X[0][idx] = h0; g_X[1][idx] = h1; g_X[2][idx] = h2;
}

__global__ void prep_W3_kernel(const float* __restrict__ W1,
                               const float* __restrict__ W2)
{
    size_t per = (size_t)N_IN * N_HID;
    size_t idx = (size_t)blockIdx.x * blockDim.x + threadIdx.x;
    if (idx >= 2 * per) return;
    float a = (idx < per) ? W1[idx] : W2[idx - per];
    __half h0, h1, h2;
    split3h(a, h0, h1, h2);
    g_W[0][idx] = h0; g_W[1][idx] = h1; g_W[2][idx] = h2;
}

// ---------------------------------------------------------------------------
// Feedforward GEMM via fp16 wmma, 6 limb-product passes (unchanged, proven)
// ---------------------------------------------------------------------------
__global__ void __launch_bounds__(256) ff_wmma_kernel(
    const float* __restrict__ b1, const float* __restrict__ b2)
{
    const int n0 = blockIdx.x * 64;
    const int m0 = blockIdx.y * 128;
    const int layer = blockIdx.z;

    __shared__ __half Xs[128][40];
    __shared__ __half Ws[32][72];

    const int tid = threadIdx.x;
    const int wid = tid >> 5;
    const int wm = wid >> 1;
    const int wn = (wid & 1) * 2;

    wmma::fragment<wmma::accumulator, 16, 16, 16, float> ctot[2][2];
#pragma unroll
    for (int i = 0; i < 2; i++)
#pragma unroll
        for (int j = 0; j < 2; j++) wmma::fill_fragment(ctot[i][j], 0.0f);

    const int PI[6] = {0, 0, 1, 0, 2, 1};
    const int PJ[6] = {0, 1, 0, 2, 0, 1};
    const float PS[6] = {1.0f, 0x1p-12f, 0x1p-12f, 0x1p-24f, 0x1p-24f, 0x1p-24f};

#pragma unroll 1
    for (int p = 0; p < 6; p++) {
        const __half* __restrict__ Xsrc = &g_X[PI[p]][0];
        const __half* __restrict__ Wsrc = &g_W[PJ[p]][(size_t)layer * N_IN * N_HID];

        wmma::fragment<wmma::accumulator, 16, 16, 16, float> acc[2][2];
#pragma unroll
        for (int i = 0; i < 2; i++)
#pragma unroll
            for (int j = 0; j < 2; j++) wmma::fill_fragment(acc[i][j], 0.0f);

#pragma unroll 1
        for (int k0 = 0; k0 < N_IN; k0 += 32) {
#pragma unroll
            for (int i = 0; i < 2; i++) {
                int idx = tid + i * 256;
                int row = idx >> 2;
                int q = (idx & 3) * 8;
                *(uint4*)&Xs[row][q] =
                    *(const uint4*)&Xsrc[(size_t)(m0 + row) * N_IN + k0 + q];
            }
            {
                int row = tid >> 3;
                int cc = (tid & 7) * 8;
                *(uint4*)&Ws[row][cc] =
                    *(const uint4*)&Wsrc[(size_t)(k0 + row) * N_HID + n0 + cc];
            }
            __syncthreads();

#pragma unroll
            for (int ks = 0; ks < 2; ks++) {
                wmma::fragment<wmma::matrix_a, 16, 16, 16, __half, wmma::row_major> af[2];
                wmma::fragment<wmma::matrix_b, 16, 16, 16, __half, wmma::row_major> bf[2];
#pragma unroll
                for (int i = 0; i < 2; i++)
                    wmma::load_matrix_sync(af[i], &Xs[(2 * wm + i) * 16][ks * 16], 40);
#pragma unroll
                for (int j = 0; j < 2; j++)
                    wmma::load_matrix_sync(bf[j], &Ws[ks * 16][(wn + j) * 16], 72);
#pragma unroll
                for (int i = 0; i < 2; i++)
#pragma unroll
                    for (int j = 0; j < 2; j++)
                        wmma::mma_sync(acc[i][j], af[i], bf[j], acc[i][j]);
            }
            __syncthreads();
        }

        const float sc = PS[p];
#pragma unroll
        for (int i = 0; i < 2; i++)
#pragma unroll
            for (int j = 0; j < 2; j++)
#pragma unroll
                for (int e = 0; e < ctot[0][0].num_elements; e++)
                    ctot[i][j].x[e] += acc[i][j].x[e] * sc;
    }

    const float* __restrict__ bias = layer ? b2 : b1;
    __shared__ float Cs[128][72];
#pragma unroll
    for (int i = 0; i < 2; i++)
#pragma unroll
        for (int j = 0; j < 2; j++)
            wmma::store_matrix_sync(&Cs[(2 * wm + i) * 16][(wn + j) * 16],
                                    ctot[i][j], 72, wmma::mem_row_major);
    __syncthreads();
    float* __restrict__ U = &g_U[layer][0][0];
#pragma unroll
    for (int e = 0; e < 32; e++) {
        int flat = tid + e * 256;
        int row = flat >> 6;
        int col = flat & 63;
        U[(size_t)(m0 + row) * N_HID + n0 + col] = Cs[row][col] + bias[n0 + col];
    }
}

// ---------------------------------------------------------------------------
// Init t=0 state (outputs + both scratches, parity 0)
// ---------------------------------------------------------------------------
__global__ void init_kernel(const float* __restrict__ mem0_1,
                            const float* __restrict__ mem0_2,
                            float* __restrict__ out)
{
    float* mems = out;
    float* spikes = out + MEMS_ELEMS;
    size_t idx = (size_t)blockIdx.x * blockDim.x + threadIdx.x;
    size_t total = (size_t)2 * BATCH * N_HID;
    if (idx >= total) return;
    int l = (int)(idx / ((size_t)BATCH * N_HID));
    size_t rem = idx % ((size_t)BATCH * N_HID);
    int b = (int)(rem / N_HID);
    int h = (int)(rem % N_HID);
    const float* m0 = l ? mem0_2 : mem0_1;
    float mv = m0[(size_t)b * N_HID + h];
    size_t o = ((size_t)(l * BATCH + b) * (FRAMES + 1)) * N_HID + h;
    __stwt(&mems[o], mv);
    __stwt(&spikes[o], 0.f);
    g_mem[0][l][b][h] = mv;
    g_sbf[0][l][b][h] = __float2half(0.f);
}

// ---------------------------------------------------------------------------
// Fused pipelined step. Grid 128 = 2 layers x 64 coltiles(32). Block 768
// (24 warps): warp = (limb(3), m-tile(4), n-tile(2)) -> 6 independent
// LDSM->MMA chains per SMSP. A via TMA bulk + mbarrier, 4 stages.
// ---------------------------------------------------------------------------
#define KC 128
#define NCH (N_HID / KC)                   // 16 chunks
#define NSTAGE 4
#define SS_STAGE_BYTES (64 * 272)          // 64 rows x 136 fp16
#define AS_STAGE_BYTES (384 * 80)          // 3 limbs x 128 k x 40 fp16 = 30720
#define SS_OFF 0
#define AS_OFF (NSTAGE * SS_STAGE_BYTES)                  // 69632
#define CS_OFF (AS_OFF + NSTAGE * AS_STAGE_BYTES)         // 192512
#define CS_TILE_BYTES (64 * 36 * 4)                       // 9216
#define MBAR_OFF (CS_OFF + 3 * CS_TILE_BYTES)             // 220160
#define STEP_SMEM_BYTES (MBAR_OFF + NSTAGE * 8 + 32)      // 220224

__device__ __forceinline__ void cpasync16(unsigned int dst, const void* src)
{
    asm volatile("cp.async.cg.shared.global [%0], [%1], 16;\n" ::"r"(dst), "l"(src));
}

__device__ __forceinline__ void mbar_init(unsigned int mbar, unsigned int count)
{
    asm volatile("mbarrier.init.shared.b64 [%0], %1;\n" ::"r"(mbar), "r"(count) : "memory");
}
__device__ __forceinline__ void mbar_expect_tx(unsigned int mbar, unsigned int bytes)
{
    asm volatile("mbarrier.arrive.expect_tx.shared.b64 _, [%0], %1;\n"
                 ::"r"(mbar), "r"(bytes) : "memory");
}
__device__ __forceinline__ void tma_bulk_1d(unsigned int dst, const void* src,
                                            unsigned int bytes, unsigned int mbar)
{
    asm volatile(
        "cp.async.bulk.shared::cta.global.mbarrier::complete_tx::bytes "
        "[%0], [%1], %2, [%3];\n"
        ::"r"(dst), "l"(src), "r"(bytes), "r"(mbar) : "memory");
}
__device__ __forceinline__ void mbar_wait(unsigned int mbar, unsigned int parity)
{
    unsigned int done;
    asm volatile(
        "{\n\t"
        ".reg .pred p;\n\t"
        "mbarrier.try_wait.parity.acquire.cta.shared::cta.b64 p, [%1], %2;\n\t"
        "selp.b32 %0, 1, 0, p;\n\t"
        "}"
        : "=r"(done) : "r"(mbar), "r"(parity) : "memory");
    if (!done) {
        asm volatile(
            "{\n\t"
            ".reg .pred P1;\n\t"
            "WAIT_LOOP_%=:\n\t"
            "mbarrier.try_wait.parity.acquire.cta.shared::cta.b64 P1, [%0], %1, 0x989680;\n\t"
            "@P1 bra.uni WAIT_DONE_%=;\n\t"
            "bra.uni WAIT_LOOP_%=;\n\t"
            "WAIT_DONE_%=:\n\t"
            "}"
            ::"r"(mbar), "r"(parity) : "memory");
    }
}

extern __shared__ char smem_buf[];

__global__ void __launch_bounds__(768) step_mma_kernel(float* __restrict__ out, int t)
{
    const int bx = blockIdx.x;
    const int layer = bx >> 6;
    const int nt = bx & 63;
    const int n0 = nt * 32;

    const int tid = threadIdx.x;
    const int wid = tid >> 5;
    const int l   = wid >> 3;      // limb 0..2
    const int w8  = wid & 7;
    const int wm  = w8 >> 1;       // 0..3 m-tile
    const int wn  = w8 & 1;        // 0..1 n-tile

    float* mems = out;
    float* spikes = out + MEMS_ELEMS;

    const __half* __restrict__ Abase =
        g_ApackP + (size_t)(layer * 64 + nt) * (16 * 3 * 128 * 40);
    const __half* __restrict__ gS = &g_sbf[t & 1][layer][0][0];
    const float* __restrict__ gM = &g_mem[t & 1][layer][0][0];

    const unsigned int smem_u32 = (unsigned int)__cvta_generic_to_shared(smem_buf);
    const unsigned int mbar0 = smem_u32 + MBAR_OFF;

    if (tid == 0) {
#pragma unroll
        for (int s = 0; s < NSTAGE; s++) mbar_init(mbar0 + s * 8, 1);
    }
    __syncthreads();

    wmma::fragment<wmma::accumulator, 16, 16, 16, float> acc;
    wmma::fill_fragment(acc, 0.0f);

    // spike copy map: first 512 threads
    const int sb = (tid & 511) >> 3;
    const int scb = tid & 7;

    auto issue_stage = [&](int c, int s) {
        if (tid == 0) {
            unsigned int mb = mbar0 + s * 8;
            mbar_expect_tx(mb, AS_STAGE_BYTES);
            tma_bulk_1d(smem_u32 + AS_OFF + s * AS_STAGE_BYTES,
                        (const char*)Abase + (size_t)c * AS_STAGE_BYTES,
                        AS_STAGE_BYTES, mb);
        }
        if (tid < 512) {
            const char* srcS = (const char*)(gS + (size_t)sb * N_HID + c * KC);
            unsigned int dstS = smem_u32 + SS_OFF + s * SS_STAGE_BYTES + sb * 272;
#pragma unroll
            for (int i = 0; i < 2; i++) {
                int cc = scb + i * 8;
                cpasync16(dstS + cc * 16, srcS + cc * 16);
            }
        }
        asm volatile("cp.async.commit_group;\n" ::: "memory");
    };

    issue_stage(0, 0);
    issue_stage(1, 1);
    issue_stage(2, 2);

#pragma unroll 1
    for (int c = 0; c < NCH; c++) {
        const int rem = NCH - 1 - c;
        if (rem >= 2)
            asm volatile("cp.async.wait_group 2;\n" ::: "memory");
        else if (rem == 1)
            asm volatile("cp.async.wait_group 1;\n" ::: "memory");
        else
            asm volatile("cp.async.wait_group 0;\n" ::: "memory");
        const int s = c & (NSTAGE - 1);
        mbar_wait(mbar0 + s * 8, (c >> 2) & 1);
        __syncthreads();

        if (c + 3 < NCH) issue_stage(c + 3, (c + 3) & (NSTAGE - 1));

        const __half* ssb = (const __half*)(smem_buf + SS_OFF + s * SS_STAGE_BYTES);
        const __half* asb = (const __half*)(smem_buf + AS_OFF + s * AS_STAGE_BYTES);

#pragma unroll
        for (int ks = 0; ks < KC / 16; ks++) {
            wmma::fragment<wmma::matrix_a, 16, 16, 16, __half, wmma::row_major> af;
            wmma::load_matrix_sync(af, ssb + (wm * 16) * 136 + ks * 16, 136);
            wmma::fragment<wmma::matrix_b, 16, 16, 16, __half, wmma::row_major> bfr;
            wmma::load_matrix_sync(bfr, asb + (l * 128 + ks * 16) * 40 + wn * 16, 40);
            wmma::mma_sync(acc, af, bfr, acc);
        }
    }

    // store raw per-limb partials; scaling happens in the epilogue
    float* Cl = (float*)(smem_buf + CS_OFF + l * CS_TILE_BYTES);
    __syncthreads();
    wmma::store_matrix_sync(Cl + (wm * 16) * 36 + wn * 16, acc, 36,
                            wmma::mem_row_major);
    __syncthreads();

    // fused LIF epilogue: p = fma(c1, 2^-12, c0) + c2*2^-24
    const float* Cs0 = (const float*)(smem_buf + CS_OFF);
    const float* Cs1 = (const float*)(smem_buf + CS_OFF + CS_TILE_BYTES);
    const float* Cs2 = (const float*)(smem_buf + CS_OFF + 2 * CS_TILE_BYTES);
    __half* gSn = &g_sbf[(t + 1) & 1][layer][0][0];
    float* gMn = &g_mem[(t + 1) & 1][layer][0][0];
#pragma unroll
    for (int e = 0; e < 3; e++) {
        int flat = tid + e * 768;   // 0..2303, guard to 2048
        if (flat < 2048) {
            int b = flat >> 5;
            int hl = flat & 31;
            int h = n0 + hl;
            float p = fmaf(Cs1[b * 36 + hl], 0x1p-12f, Cs0[b * 36 + hl])
                      + Cs2[b * 36 + hl] * 0x1p-24f;
            float u = __ldcs(&g_U[layer][b * FRAMES + t][h]);
            size_t row_t1 =
                ((size_t)(layer * BATCH + b) * (FRAMES + 1) + t + 1) * N_HID + h;
            float mprev = gM[(size_t)b * N_HID + h];
            float sprev = __half2float(gS[(size_t)b * N_HID + h]);
            float y = tanhf(ALPHA * p + (1.0f - ALPHA) * u);
            float mn = DECAY * mprev - THR * (1.0f - sprev) + y;
            float sn = (mn > THR) ? 1.0f : 0.0f;
            __stwt(&mems[row_t1], mn);
            __stwt(&spikes[row_t1], sn);
            gMn[(size_t)b * N_HID + h] = mn;
            gSn[(size_t)b * N_HID + h] = __float2half(sn);
        }
    }
}

// ---------------------------------------------------------------------------
// Launch. Inputs: x, W_in1, A1, b1, W_in2, A2, b2, mem0_1, mem0_2
// ---------------------------------------------------------------------------
extern "C" void kernel_launch(void* const* d_in, const int* in_sizes, int n_in,
                              void* d_out, int out_size)
{
    const float* x      = (const float*)d_in[0];
    const float* W_in1  = (const float*)d_in[1];
    const float* A1     = (const float*)d_in[2];
    const float* b1     = (const float*)d_in[3];
    const float* W_in2  = (const float*)d_in[4];
    const float* A2     = (const float*)d_in[5];
    const float* b2     = (const float*)d_in[6];
    const float* mem0_1 = (const float*)d_in[7];
    const float* mem0_2 = (const float*)d_in[8];
    float* out = (float*)d_out;

    cudaFuncSetAttribute(step_mma_kernel,
                         cudaFuncAttributeMaxDynamicSharedMemorySize,
                         STEP_SMEM_BYTES);

    // limb packs
    {
        size_t n = (size_t)2 * N_HID * N_HID;
        prep_A3_kernel<<<(unsigned)((n + 255) / 256), 256>>>(A1, A2);
    }
    {
        size_t n = (size_t)BATCH * FRAMES * N_IN;
        prep_x3_kernel<<<(unsigned)((n + 255) / 256), 256>>>(x);
    }
    {
        size_t n = (size_t)2 * N_IN * N_HID;
        prep_W3_kernel<<<(unsigned)((n + 255) / 256), 256>>>(W_in1, W_in2);
    }

    // Feedforward drive on tensor cores (includes bias)
    {
        dim3 grid(N_HID / 64, (BATCH * FRAMES) / 128, 2);
        ff_wmma_kernel<<<grid, 256>>>(b1, b2);
    }

    // t=0 state
    {
        int total = 2 * BATCH * N_HID;
        init_kernel<<<(total + 255) / 256, 256>>>(mem0_1, mem0_2, out);
    }

    // Sequential time loop
    for (int t = 0; t < FRAMES; t++) {
        step_mma_kernel<<<128, 768, STEP_SMEM_BYTES>>>(out, t);
    }
}